// round 1
// baseline (speedup 1.0000x reference)
#include <cuda_runtime.h>

// RNN-T transducer loss forward.
// B=16, T=200, U=101 (labels 100 + terminal), A=512, blank=0.
//
// 3 kernels:
//  1) gather: full-chip, pulls blk = lp[...,0] and emit = lp[...,label[u]]
//     into compact padded scratch [B][T][104] (2.6MB, L2-resident).
//  2) lattice: 16 CTAs (one per batch), 128 threads. Stage blk/emit into
//     166KB smem, then anti-diagonal wavefront over the alpha recurrence:
//       alpha[t,u] = LAE(alpha[t-1,u]+blk[t-1,u], alpha[t,u-1]+emit[t,u-1])
//     Thread u owns column u; step s computes cell (t=s-u, u). One
//     __syncthreads per diagonal, double-buffered alpha row in smem.
//  3) reduce: fixed-order sum of per-batch log_p -> mean(-log_p) scalar.

#define BQ 16
#define TM 200
#define UM 101
#define AA 512
#define UP 104   // padded U (float4-aligned, odd diagonal stride -> bank-conflict-free)

__device__ __align__(16) float g_blk [BQ][TM][UP];
__device__ __align__(16) float g_emit[BQ][TM][UP];
__device__ float g_logp[BQ];

__global__ void tl_gather_kernel(const float* __restrict__ lp,
                                 const int*   __restrict__ labels)
{
    int i = blockIdx.x * blockDim.x + threadIdx.x;
    const int total = BQ * TM * UM;
    if (i >= total) return;
    int u  = i % UM;
    int bt = i / UM;
    int t  = bt % TM;
    int b  = bt / TM;
    // lab[u] = labels[b][u] for u<100, blank(0) for the terminal column
    int lab = (u < UM - 1) ? labels[b * (UM - 1) + u] : 0;
    size_t base = (size_t)i * AA;        // i == ((b*TM + t)*UM + u)
    float bv = __ldg(lp + base);         // blank channel
    float ev = __ldg(lp + base + lab);   // label channel
    g_blk [b][t][u] = bv;
    g_emit[b][t][u] = ev;
}

__device__ __forceinline__ float lae(float x, float y)
{
    float m = fmaxf(x, y);
    float d = fminf(x, y) - m;           // <= 0, finite
    return m + __logf(1.0f + __expf(d));
}

__global__ __launch_bounds__(128, 1)
void tl_lattice_kernel(const int* __restrict__ Tarr,
                       const int* __restrict__ Uarr)
{
    extern __shared__ float sm[];
    float* s_blk  = sm;                  // [TM][UP]
    float* s_emit = sm + TM * UP;        // [TM][UP]
    __shared__ float s_alpha[2][UP];

    const int b   = blockIdx.x;
    const int tid = threadIdx.x;

    // Stage compact blk/emit for this batch into shared (coalesced float4).
    {
        const float4* gb  = (const float4*)&g_blk [b][0][0];
        const float4* ge  = (const float4*)&g_emit[b][0][0];
        float4* sb4 = (float4*)s_blk;
        float4* se4 = (float4*)s_emit;
        const int n4 = TM * UP / 4;      // 5200
        for (int k = tid; k < n4; k += 128) {
            sb4[k] = gb[k];
            se4[k] = ge[k];
        }
    }
    const int Tb = Tarr[b];
    const int Ub = Uarr[b];
    __syncthreads();

    const int u = tid;
    float own = 0.0f;                    // alpha[t-1, u] (own column, prev step)
    const int smax = (Tb - 1) + Ub;      // step producing cell (Tb-1, Ub)

    for (int s = 0; s <= smax; ++s) {
        const int w = s & 1;
        const int r = w ^ 1;
        const int t = s - u;
        const bool active = (u <= Ub) && (t >= 0) && (t < Tb);
        if (active) {
            float val;
            if (t == 0) {
                // alpha[0,u] = alpha[0,u-1] + emit[0,u-1]; alpha[0,0] = 0
                val = (u == 0) ? 0.0f
                               : s_alpha[r][u - 1] + s_emit[u - 1];
            } else if (u == 0) {
                // alpha[t,0] = alpha[t-1,0] + blk[t-1,0]
                val = own + s_blk[(t - 1) * UP];
            } else {
                float ver = own + s_blk[(t - 1) * UP + u];
                float hor = s_alpha[r][u - 1] + s_emit[t * UP + (u - 1)];
                val = lae(ver, hor);
            }
            own = val;
            s_alpha[w][u] = val;
            if (t == Tb - 1 && u == Ub) {
                // log_p = alpha[T-1, U] + blk[T-1, U]
                g_logp[b] = val + s_blk[(Tb - 1) * UP + Ub];
            }
        }
        __syncthreads();
    }
}

__global__ void tl_reduce_kernel(float* __restrict__ out)
{
    if (threadIdx.x == 0 && blockIdx.x == 0) {
        float s = 0.0f;
        #pragma unroll
        for (int b = 0; b < BQ; ++b) s += g_logp[b];
        out[0] = -s / (float)BQ;
    }
}

extern "C" void kernel_launch(void* const* d_in, const int* in_sizes, int n_in,
                              void* d_out, int out_size)
{
    const float* lp     = (const float*)d_in[0];
    const int*   labels = (const int*)  d_in[1];
    const int*   Tarr   = (const int*)  d_in[2];
    const int*   Uarr   = (const int*)  d_in[3];
    float* out = (float*)d_out;

    const int smem_bytes = 2 * TM * UP * (int)sizeof(float);  // 166,400
    cudaFuncSetAttribute(tl_lattice_kernel,
                         cudaFuncAttributeMaxDynamicSharedMemorySize,
                         smem_bytes);

    const int total = BQ * TM * UM;
    tl_gather_kernel<<<(total + 255) / 256, 256>>>(lp, labels);
    tl_lattice_kernel<<<BQ, 128, smem_bytes>>>(Tarr, Uarr);
    tl_reduce_kernel<<<1, 32>>>(out);
}